// round 2
// baseline (speedup 1.0000x reference)
#include <cuda_runtime.h>
#include <cstdint>

// Problem constants
#define NN 50000
#define EE 800000
#define HH 128
#define TH 384        // 3*H

// x_h scratch: [N][384] fp32 = 76.8 MB (device global scratch, no allocation)
__device__ __align__(16) float g_xh[(size_t)NN * TH];

// ---------------- PTX helpers ----------------
#define PACK2(d, lo, hi) \
    asm volatile("mov.b64 %0, {%1, %2};" : "=l"(d) : "f"(lo), "f"(hi))
#define UNPACK2(lo, hi, s) \
    asm volatile("mov.b64 {%0, %1}, %2;" : "=f"(lo), "=f"(hi) : "l"(s))
#define FMA2(c_, a_, b_) \
    asm volatile("fma.rn.f32x2 %0, %1, %2, %0;" : "+l"(c_) : "l"(a_), "l"(b_))
#define RED4(p_, v_) \
    asm volatile("red.global.add.v4.f32 [%0], {%1, %2, %3, %4};" \
                 :: "l"(p_), "f"((v_).x), "f"((v_).y), "f"((v_).z), "f"((v_).w) : "memory")
#define CP_ASYNC16(dst_s, src_g) \
    asm volatile("cp.async.cg.shared.global [%0], [%1], 16;" :: "r"(dst_s), "l"(src_g))
#define CP_COMMIT() asm volatile("cp.async.commit_group;")
#define CP_WAIT(n_)  asm volatile("cp.async.wait_group %0;" :: "n"(n_))

// ---------------- zero output ----------------
__global__ void zero_kernel(float4* __restrict__ p, long long n4) {
    long long i = (long long)blockIdx.x * blockDim.x + threadIdx.x;
    if (i < n4) p[i] = make_float4(0.f, 0.f, 0.f, 0.f);
}

// ---------------- node kernel: x_h = Lin2(ScaledSiLU(Lin1(x))) ----------------
// 384 threads, 16 nodes per block, 3125 blocks.
__global__ __launch_bounds__(384) void node_kernel(
    const float* __restrict__ x, const float* __restrict__ W1,
    const float* __restrict__ b1, const float* __restrict__ W2,
    const float* __restrict__ b2)
{
    __shared__ __align__(16) float xs[128 * 16];   // x transposed [k][n], 8 KB
    __shared__ __align__(16) float w1s[128 * 64];  // W1, 32 KB
    __shared__ __align__(16) float hs[64 * 20];    // h transposed [k][n] (pad 20), 5 KB

    const int t = threadIdx.x;
    const int node0 = blockIdx.x * 16;

    for (int i = t; i < 8192; i += 384) w1s[i] = W1[i];

    const float4* x4 = (const float4*)x;
    for (int idx = t; idx < 512; idx += 384) {
        int n = idx & 15, kq = idx >> 4;
        float4 v = x4[(size_t)(node0 + n) * 32 + kq];
        xs[(kq * 4 + 0) * 16 + n] = v.x;
        xs[(kq * 4 + 1) * 16 + n] = v.y;
        xs[(kq * 4 + 2) * 16 + n] = v.z;
        xs[(kq * 4 + 3) * 16 + n] = v.w;
    }
    __syncthreads();

    // phase 1: h[n][c] = ScaledSiLU(x@W1 + b1), c in [0,64)
    for (int idx = t; idx < 1024; idx += 384) {
        int n = idx & 15, c = idx >> 4;
        float acc = b1[c];
#pragma unroll 8
        for (int k = 0; k < 128; k++) acc += xs[k * 16 + n] * w1s[k * 64 + c];
        float hv = acc / (1.f + __expf(-acc)) * 1.6666666666666667f;  // SiLU / 0.6
        hs[c * 20 + n] = hv;
    }
    __syncthreads();

    // phase 2: x_h[n][c] = h@W2 + b2, c = t in [0,384)
    const int c = t;
    unsigned long long acc2[8];
#pragma unroll
    for (int p = 0; p < 8; p++) acc2[p] = 0ull;  // packed (0.f, 0.f)

#pragma unroll 4
    for (int k = 0; k < 64; k++) {
        float w = W2[k * 384 + c];
        unsigned long long wp; PACK2(wp, w, w);
        const unsigned long long* hp = (const unsigned long long*)&hs[k * 20];
#pragma unroll
        for (int p = 0; p < 8; p++) {
            unsigned long long hv = hp[p];
            FMA2(acc2[p], hv, wp);
        }
    }
    const float bc = b2[c];
#pragma unroll
    for (int p = 0; p < 8; p++) {
        float lo, hi; UNPACK2(lo, hi, acc2[p]);
        g_xh[(size_t)(node0 + 2 * p) * 384 + c] = lo + bc;
        g_xh[(size_t)(node0 + 2 * p + 1) * 384 + c] = hi + bc;
    }
}

// ---------------- edge kernel: GEMM(rbf@We) fused with gather/scatter ----------------
// 256 threads, 32 edges per block, full 384 columns in registers.
// Thread map: eg = t&7 (4 edges each), cg = t>>3 (cols cg*4 + {0..3} in each of 3 chunks).
#define KT 8           // k-chunk for We double buffer
#define NCH 16         // 128 / KT

__global__ __launch_bounds__(256, 2) void edge_kernel(
    const float* __restrict__ edge_rbf, const float* __restrict__ edge_vector,
    const int* __restrict__ edge_index, const float* __restrict__ We,
    const float* __restrict__ be, const float* __restrict__ vec,
    float* __restrict__ d_x, float* __restrict__ d_vec)
{
    __shared__ __align__(16) float As[128 * 32];          // 16 KB, transposed [k][e]
    __shared__ __align__(16) float Ws[2 * KT * 384];      // 24 KB double-buffered We chunks
    __shared__ int   js[32], is_[32];
    __shared__ float evs[96];               // [32][3]

    const int t = threadIdx.x;
    const int e0 = blockIdx.x * 32;
    const int eg = t & 7;
    const int c0 = (t >> 3) * 4;

    if (t < 32) {
        js[t]  = edge_index[e0 + t];           // row 0: j (source)
        is_[t] = edge_index[EE + e0 + t];      // row 1: i (target)
    }
    if (t < 96) evs[t] = edge_vector[(size_t)e0 * 3 + t];

    // load + transpose the edge_rbf tile
    const float4* rbf4 = (const float4*)edge_rbf;
#pragma unroll
    for (int r = 0; r < 4; r++) {
        int idx = t + r * 256;
        int e = idx & 31, kq = idx >> 5;
        float4 v = rbf4[(size_t)(e0 + e) * 32 + kq];
        As[(kq * 4 + 0) * 32 + e] = v.x;
        As[(kq * 4 + 1) * 32 + e] = v.y;
        As[(kq * 4 + 2) * 32 + e] = v.z;
        As[(kq * 4 + 3) * 32 + e] = v.w;
    }

    // prefetch We chunk 0
    {
        const float* src = We;
        float* dstb = Ws;
#pragma unroll
        for (int r = 0; r < 3; r++) {
            int fi = t + r * 256;          // 0..767 float4s
            int k = fi / 96, q = fi % 96;
            unsigned ds = (unsigned)__cvta_generic_to_shared(dstb + k * 384 + q * 4);
            CP_ASYNC16(ds, src + (size_t)k * 384 + q * 4);
        }
        CP_COMMIT();
    }

    unsigned long long acc[4][3][2];
#pragma unroll
    for (int e = 0; e < 4; e++)
#pragma unroll
        for (int u = 0; u < 3; u++) { acc[e][u][0] = 0ull; acc[e][u][1] = 0ull; }

    for (int ch = 0; ch < NCH; ch++) {
        if (ch + 1 < NCH) {
            const float* src = We + (size_t)(ch + 1) * KT * 384;
            float* dstb = Ws + ((ch + 1) & 1) * (KT * 384);
#pragma unroll
            for (int r = 0; r < 3; r++) {
                int fi = t + r * 256;
                int k = fi / 96, q = fi % 96;
                unsigned ds = (unsigned)__cvta_generic_to_shared(dstb + k * 384 + q * 4);
                CP_ASYNC16(ds, src + (size_t)k * 384 + q * 4);
            }
            CP_COMMIT();
            CP_WAIT(1);
        } else {
            CP_WAIT(0);
        }
        __syncthreads();

        const float* Wb = Ws + (ch & 1) * (KT * 384);
#pragma unroll
        for (int kk = 0; kk < KT; kk++) {
            const int k = ch * KT + kk;
            float4 av = *(const float4*)&As[k * 32 + eg * 4];
            unsigned long long a0, a1, a2, a3;
            PACK2(a0, av.x, av.x); PACK2(a1, av.y, av.y);
            PACK2(a2, av.z, av.z); PACK2(a3, av.w, av.w);
            const float* wr = Wb + kk * 384;
            ulonglong2 w0 = *(const ulonglong2*)(wr + c0);
            ulonglong2 w1 = *(const ulonglong2*)(wr + c0 + 128);
            ulonglong2 w2 = *(const ulonglong2*)(wr + c0 + 256);
            FMA2(acc[0][0][0], a0, w0.x); FMA2(acc[0][0][1], a0, w0.y);
            FMA2(acc[0][1][0], a0, w1.x); FMA2(acc[0][1][1], a0, w1.y);
            FMA2(acc[0][2][0], a0, w2.x); FMA2(acc[0][2][1], a0, w2.y);
            FMA2(acc[1][0][0], a1, w0.x); FMA2(acc[1][0][1], a1, w0.y);
            FMA2(acc[1][1][0], a1, w1.x); FMA2(acc[1][1][1], a1, w1.y);
            FMA2(acc[1][2][0], a1, w2.x); FMA2(acc[1][2][1], a1, w2.y);
            FMA2(acc[2][0][0], a2, w0.x); FMA2(acc[2][0][1], a2, w0.y);
            FMA2(acc[2][1][0], a2, w1.x); FMA2(acc[2][1][1], a2, w1.y);
            FMA2(acc[2][2][0], a2, w2.x); FMA2(acc[2][2][1], a2, w2.y);
            FMA2(acc[3][0][0], a3, w0.x); FMA2(acc[3][0][1], a3, w0.y);
            FMA2(acc[3][1][0], a3, w1.x); FMA2(acc[3][1][1], a3, w1.y);
            FMA2(acc[3][2][0], a3, w2.x); FMA2(acc[3][2][1], a3, w2.y);
        }
        __syncthreads();
    }

    // ---------------- epilogue: xm, vec_ji, scatter ----------------
    const float s3 = 0.5773502691896258f;    // 1/sqrt(3)
    const float sH = 0.08838834764831845f;   // 1/sqrt(128)
    float4 be0 = *(const float4*)(be + c0);
    float4 be1 = *(const float4*)(be + c0 + 128);
    float4 be2 = *(const float4*)(be + c0 + 256);

#pragma unroll
    for (int e = 0; e < 4; e++) {
        const int ee = eg * 4 + e;
        const int j = js[ee], i = is_[ee];

        float a1[4], a2[4], a3[4];
        UNPACK2(a1[0], a1[1], acc[e][0][0]); UNPACK2(a1[2], a1[3], acc[e][0][1]);
        UNPACK2(a2[0], a2[1], acc[e][1][0]); UNPACK2(a2[2], a2[3], acc[e][1][1]);
        UNPACK2(a3[0], a3[1], acc[e][2][0]); UNPACK2(a3[2], a3[3], acc[e][2][1]);

        const float* xh = g_xh + (size_t)j * 384;
        float4 x1 = *(const float4*)(xh + c0);
        float4 x2 = *(const float4*)(xh + c0 + 128);
        float4 x3 = *(const float4*)(xh + c0 + 256);

        float m1[4], m2[4];
        m1[0] = (a1[0] + be0.x) * x1.x * s3;
        m1[1] = (a1[1] + be0.y) * x1.y * s3;
        m1[2] = (a1[2] + be0.z) * x1.z * s3;
        m1[3] = (a1[3] + be0.w) * x1.w * s3;
        m2[0] = (a2[0] + be1.x) * x2.x * s3;
        m2[1] = (a2[1] + be1.y) * x2.y * s3;
        m2[2] = (a2[2] + be1.z) * x2.z * s3;
        m2[3] = (a2[3] + be1.w) * x2.w * s3;
        float4 ox;
        ox.x = (a3[0] + be2.x) * x3.x * s3;
        ox.y = (a3[1] + be2.y) * x3.y * s3;
        ox.z = (a3[2] + be2.z) * x3.z * s3;
        ox.w = (a3[3] + be2.w) * x3.w * s3;

        const float ev0 = evs[ee * 3 + 0];
        const float ev1 = evs[ee * 3 + 1];
        const float ev2 = evs[ee * 3 + 2];

        const float* vp = vec + (size_t)j * 384;
        float* dvp = d_vec + (size_t)i * 384;

#pragma unroll
        for (int d = 0; d < 3; d++) {
            const float evd = (d == 0) ? ev0 : (d == 1) ? ev1 : ev2;
            float4 vj = *(const float4*)(vp + d * 128 + c0);
            float4 o;
            o.x = (m1[0] * vj.x + m2[0] * evd) * sH;
            o.y = (m1[1] * vj.y + m2[1] * evd) * sH;
            o.z = (m1[2] * vj.z + m2[2] * evd) * sH;
            o.w = (m1[3] * vj.w + m2[3] * evd) * sH;
            RED4(dvp + d * 128 + c0, o);
        }
        RED4(d_x + (size_t)i * 128 + c0, ox);
    }
}

// ---------------- launch ----------------
extern "C" void kernel_launch(void* const* d_in, const int* in_sizes, int n_in,
                              void* d_out, int out_size)
{
    const float *x = nullptr, *vec = nullptr, *erbf = nullptr, *evec = nullptr;
    const float *W1 = nullptr, *b1 = nullptr, *W2 = nullptr, *b2 = nullptr;
    const float *We = nullptr, *be = nullptr;
    const int* eidx = nullptr;

    int seen384 = 0;
    for (int idx = 0; idx < n_in; idx++) {
        int s = in_sizes[idx];
        const void* p = d_in[idx];
        switch (s) {
            case 6400000:   x    = (const float*)p; break;       // N*H
            case 19200000:  vec  = (const float*)p; break;       // N*3*H
            case 102400000: erbf = (const float*)p; break;       // E*F
            case 2400000:   evec = (const float*)p; break;       // E*3
            case 1600000:   eidx = (const int*)p; break;         // 2*E int32 (jax x64 off)
            case 8192:      W1   = (const float*)p; break;       // H x H/2
            case 64:        b1   = (const float*)p; break;
            case 24576:     W2   = (const float*)p; break;       // H/2 x 3H
            case 49152:     We   = (const float*)p; break;       // F x 3H
            case 384:
                if (seen384 == 0) b2 = (const float*)p; else be = (const float*)p;
                seen384++;
                break;
            default: break;
        }
    }

    float* out   = (float*)d_out;
    float* d_x   = out;                               // [N,128]
    float* d_vec = out + (size_t)NN * HH;             // [N,3,128]

    // 1. zero the output (poisoned by harness)
    long long n4 = out_size / 4;
    zero_kernel<<<(unsigned)((n4 + 255) / 256), 256>>>((float4*)out, n4);
    // 2. node MLP -> g_xh
    node_kernel<<<NN / 16, 384>>>(x, W1, b1, W2, b2);
    // 3. fused edge GEMM + message + scatter
    edge_kernel<<<EE / 32, 256>>>(erbf, evec, eidx, We, be, vec, d_x, d_vec);
}

// round 5
// speedup vs baseline: 1.3804x; 1.3804x over previous
#include <cuda_runtime.h>
#include <cuda_bf16.h>
#include <cstdint>

#define NN 50000
#define EE 800000
#define HH 128
#define TH 384

// scratch: x_h [N][384] fp32; We pre-split bf16 hi/lo, chunked [kc][half][n][32B]
__device__ __align__(16) float g_xh[(size_t)NN * TH];
__device__ __align__(16) unsigned char g_WeB[8 * 2 * 384 * 32];   // 196608 B

// ---------------- PTX helpers ----------------
#define PACK2(d, lo, hi) \
    asm volatile("mov.b64 %0, {%1, %2};" : "=l"(d) : "f"(lo), "f"(hi))
#define UNPACK2(lo, hi, s) \
    asm volatile("mov.b64 {%0, %1}, %2;" : "=f"(lo), "=f"(hi) : "l"(s))
#define FMA2(c_, a_, b_) \
    asm volatile("fma.rn.f32x2 %0, %1, %2, %0;" : "+l"(c_) : "l"(a_), "l"(b_))
#define RED4(p_, v_) \
    asm volatile("red.global.add.v4.f32 [%0], {%1, %2, %3, %4};" \
                 :: "l"(p_), "f"((v_).x), "f"((v_).y), "f"((v_).z), "f"((v_).w) : "memory")
#define CP_ASYNC16(dst_s, src_g) \
    asm volatile("cp.async.cg.shared.global [%0], [%1], 16;" :: "r"(dst_s), "l"(src_g))
#define CP_COMMIT() asm volatile("cp.async.commit_group;")
#define CP_WAIT0()  asm volatile("cp.async.wait_group 0;")
#define CP_WAIT1()  asm volatile("cp.async.wait_group 1;")

#define LDSM4(f_, addr_) \
    asm volatile("ldmatrix.sync.aligned.m8n8.x4.shared.b16 {%0,%1,%2,%3}, [%4];" \
        : "=r"((f_)[0]), "=r"((f_)[1]), "=r"((f_)[2]), "=r"((f_)[3]) : "r"(addr_))
#define MMA(c_, a_, b0_, b1_) \
    asm volatile("mma.sync.aligned.m16n8k16.row.col.f32.bf16.bf16.f32 " \
        "{%0,%1,%2,%3}, {%4,%5,%6,%7}, {%8,%9}, {%0,%1,%2,%3};" \
        : "+f"((c_)[0]), "+f"((c_)[1]), "+f"((c_)[2]), "+f"((c_)[3]) \
        : "r"((a_)[0]), "r"((a_)[1]), "r"((a_)[2]), "r"((a_)[3]), "r"(b0_), "r"(b1_))

// ---------------- zero output ----------------
__global__ void zero_kernel(float4* __restrict__ p, long long n4) {
    long long i = (long long)blockIdx.x * blockDim.x + threadIdx.x;
    if (i < n4) p[i] = make_float4(0.f, 0.f, 0.f, 0.f);
}

// ---------------- prep: We [K=128][N=384] fp32 -> bf16 hi/lo chunks ----------------
// layout: g_WeB + kc*24576 + half*12288 + n*32 + ((k>>3)&1)*16 + (k&7)*2
__global__ void prep_we(const float* __restrict__ We) {
    int idx = blockIdx.x * 256 + threadIdx.x;    // 384*128
    if (idx >= 384 * 128) return;
    int n = idx >> 7, k = idx & 127;
    float v = We[(size_t)k * 384 + n];
    __nv_bfloat16 h = __float2bfloat16(v);
    __nv_bfloat16 l = __float2bfloat16(v - __bfloat162float(h));
    uint32_t off = (uint32_t)((k >> 4) * 24576 + n * 32 + ((k >> 3) & 1) * 16 + (k & 7) * 2);
    *(unsigned short*)(g_WeB + off)          = __bfloat16_as_ushort(h);
    *(unsigned short*)(g_WeB + off + 12288)  = __bfloat16_as_ushort(l);
}

// ---------------- node kernel (unchanged; FFMA2 path) ----------------
__global__ __launch_bounds__(384) void node_kernel(
    const float* __restrict__ x, const float* __restrict__ W1,
    const float* __restrict__ b1, const float* __restrict__ W2,
    const float* __restrict__ b2)
{
    __shared__ __align__(16) float xs[128 * 16];
    __shared__ __align__(16) float w1s[128 * 64];
    __shared__ __align__(16) float hs[64 * 20];

    const int t = threadIdx.x;
    const int node0 = blockIdx.x * 16;

    for (int i = t; i < 8192; i += 384) w1s[i] = W1[i];
    const float4* x4 = (const float4*)x;
    for (int idx = t; idx < 512; idx += 384) {
        int n = idx & 15, kq = idx >> 4;
        float4 v = x4[(size_t)(node0 + n) * 32 + kq];
        xs[(kq * 4 + 0) * 16 + n] = v.x;
        xs[(kq * 4 + 1) * 16 + n] = v.y;
        xs[(kq * 4 + 2) * 16 + n] = v.z;
        xs[(kq * 4 + 3) * 16 + n] = v.w;
    }
    __syncthreads();

    for (int idx = t; idx < 1024; idx += 384) {
        int n = idx & 15, c = idx >> 4;
        float acc = b1[c];
#pragma unroll 8
        for (int k = 0; k < 128; k++) acc += xs[k * 16 + n] * w1s[k * 64 + c];
        float hv = acc / (1.f + __expf(-acc)) * 1.6666666666666667f;
        hs[c * 20 + n] = hv;
    }
    __syncthreads();

    const int c = t;
    unsigned long long acc2[8];
#pragma unroll
    for (int p = 0; p < 8; p++) acc2[p] = 0ull;
#pragma unroll 4
    for (int k = 0; k < 64; k++) {
        float w = W2[k * 384 + c];
        unsigned long long wp; PACK2(wp, w, w);
        const unsigned long long* hp = (const unsigned long long*)&hs[k * 20];
#pragma unroll
        for (int p = 0; p < 8; p++) { unsigned long long hv = hp[p]; FMA2(acc2[p], hv, wp); }
    }
    const float bc = b2[c];
#pragma unroll
    for (int p = 0; p < 8; p++) {
        float lo, hi; UNPACK2(lo, hi, acc2[p]);
        g_xh[(size_t)(node0 + 2 * p) * 384 + c] = lo + bc;
        g_xh[(size_t)(node0 + 2 * p + 1) * 384 + c] = hi + bc;
    }
}

// ---------------- edge kernel: mma.sync bf16-split GEMM + fused epilogue ----------------
// 512 threads, 64 edges/block. Warp w: mband = w&3 (16 rows), nslice = w>>2 (96 cols).
// smem (dynamic):
//   [0:256)     js[64]        [256:512) is[64]
//   [512:1280)  evs[192]      [1280:2816) bes[384]
//   [4096:20480)   A hi  64x128 bf16 (swizzled)
//   [20480:36864)  A lo
//   [36864:110592) B double buffer: buf b at +b*36864 { hi 384x48B, lo +18432 }
//   staging (after MMA): fp32 [32][388] at 36864 (49664 B, reuses B)
#define A_OFF 4096
#define B_OFF 36864
#define BBUF  36864
#define EDGE_SMEM 110592
#define STG_STRIDE 388

__global__ __launch_bounds__(512, 1) void edge_kernel(
    const float* __restrict__ edge_rbf, const float* __restrict__ edge_vector,
    const int* __restrict__ edge_index, const float* __restrict__ be,
    const float* __restrict__ vec, float* __restrict__ d_x, float* __restrict__ d_vec)
{
    extern __shared__ __align__(16) unsigned char sm[];
    const uint32_t smb = (uint32_t)__cvta_generic_to_shared(sm);
    const int tid = threadIdx.x;
    const int wid = tid >> 5;
    const int lane = tid & 31;
    const int e0 = blockIdx.x * 64;

    int* js   = (int*)(sm);
    int* is_  = (int*)(sm + 256);
    float* evs = (float*)(sm + 512);
    float* bes = (float*)(sm + 1280);

    if (tid < 64) {
        js[tid]  = edge_index[e0 + tid];
        is_[tid] = edge_index[EE + e0 + tid];
    }
    if (tid < 192) evs[tid] = edge_vector[(size_t)e0 * 3 + tid];
    if (tid >= 128 && tid < 512) bes[tid - 128] = be[tid - 128];

    // ---- A: load fp32 rbf, split bf16 hi/lo, swizzled store ----
    const float4* rbf4 = (const float4*)edge_rbf;
#pragma unroll
    for (int r = 0; r < 4; r++) {
        int fid = tid + r * 512;            // 0..2047
        int e = fid >> 5, q = fid & 31;     // edge row, float4 index (k0 = q*4)
        float4 v = rbf4[(size_t)(e0 + e) * 32 + q];
        float vv[4] = {v.x, v.y, v.z, v.w};
        unsigned short hb[4], lb[4];
#pragma unroll
        for (int u = 0; u < 4; u++) {
            __nv_bfloat16 h = __float2bfloat16(vv[u]);
            __nv_bfloat16 l = __float2bfloat16(vv[u] - __bfloat162float(h));
            hb[u] = __bfloat16_as_ushort(h);
            lb[u] = __bfloat16_as_ushort(l);
        }
        uint2 ph = make_uint2((uint32_t)hb[0] | ((uint32_t)hb[1] << 16),
                              (uint32_t)hb[2] | ((uint32_t)hb[3] << 16));
        uint2 pl = make_uint2((uint32_t)lb[0] | ((uint32_t)lb[1] << 16),
                              (uint32_t)lb[2] | ((uint32_t)lb[3] << 16));
        uint32_t addr = (uint32_t)(e * 256 + (((q >> 1) ^ (e & 7)) << 4) + (q & 1) * 8);
        *(uint2*)(sm + A_OFF + addr)         = ph;
        *(uint2*)(sm + A_OFF + 16384 + addr) = pl;
    }

    // ---- prefetch B chunk 0 ----
    {
#pragma unroll
        for (int r = 0; r < 3; r++) {
            int id = tid + r * 512;                   // 0..1535
            int half = id >= 768, rem = id - half * 768;
            int n = rem >> 1, u = rem & 1;
            CP_ASYNC16(smb + B_OFF + half * 18432 + n * 48 + u * 16,
                       g_WeB + half * 12288 + n * 32 + u * 16);
        }
        CP_COMMIT();
    }

    // ---- per-warp frag addressing ----
    const int m0 = (wid & 3) * 16;
    const int n0 = (wid >> 2) * 96;
    const int am = m0 + (lane & 15);
    const uint32_t a_row = smb + A_OFF + am * 256;
    const int a_kpar = lane >> 4;                 // k-half select
    const int a_sw = lane & 7;                    // swizzle key (== am & 7)
    // B: row = n0 + (lane>>4)*8 + (lane&7), +16B for k-high half
    const uint32_t b_row = (uint32_t)((n0 + ((lane >> 4) << 3) + (lane & 7)) * 48
                                      + (((lane >> 3) & 1) << 4));

    float acc[48];
#pragma unroll
    for (int i = 0; i < 48; i++) acc[i] = 0.f;

    for (int kc = 0; kc < 8; kc++) {
        if (kc < 7) {
            const unsigned char* src = g_WeB + (size_t)(kc + 1) * 24576;
            uint32_t dst = smb + B_OFF + ((kc + 1) & 1) * BBUF;
#pragma unroll
            for (int r = 0; r < 3; r++) {
                int id = tid + r * 512;
                int half = id >= 768, rem = id - half * 768;
                int n = rem >> 1, u = rem & 1;
                CP_ASYNC16(dst + half * 18432 + n * 48 + u * 16,
                           src + half * 12288 + n * 32 + u * 16);
            }
            CP_COMMIT();
            CP_WAIT1();
        } else {
            CP_WAIT0();
        }
        __syncthreads();

        uint32_t ah[4], al[4];
        {
            uint32_t aaddr = a_row + (((kc * 2 + a_kpar) ^ a_sw) << 4);
            LDSM4(ah, aaddr);
            LDSM4(al, aaddr + 16384);
        }
        const uint32_t bb = smb + B_OFF + (kc & 1) * BBUF + b_row;
#pragma unroll
        for (int p = 0; p < 6; p++) {
            uint32_t bh[4], bl[4];
            uint32_t baddr = bb + p * 768;            // 16 rows * 48B per pair
            LDSM4(bh, baddr);
            LDSM4(bl, baddr + 18432);
            float* cA = acc + p * 8;
            float* cB = acc + p * 8 + 4;
            MMA(cA, ah, bh[0], bh[1]);
            MMA(cA, al, bh[0], bh[1]);
            MMA(cA, ah, bl[0], bl[1]);
            MMA(cB, ah, bh[2], bh[3]);
            MMA(cB, al, bh[2], bh[3]);
            MMA(cB, ah, bl[2], bl[3]);
        }
        __syncthreads();
    }

    // ---------------- epilogue: stage 32 edges at a time, fused scatter ----------------
    const float s3 = 0.5773502691896258f;    // 1/sqrt(3)
    const float sH = 0.08838834764831845f;   // 1/sqrt(128)
    float* stg = (float*)(sm + B_OFF);
    const int mband = wid & 3;
    const int g = lane >> 2;
    const int cq = (lane & 3) * 2;

#pragma unroll
    for (int wave = 0; wave < 2; wave++) {
        if ((mband >> 1) == wave) {
            const int m0l = (mband & 1) * 16;
#pragma unroll
            for (int nt = 0; nt < 12; nt++) {
                int col = n0 + nt * 8 + cq;
                *(float2*)&stg[(m0l + g) * STG_STRIDE + col] =
                    make_float2(acc[nt * 4 + 0], acc[nt * 4 + 1]);
                *(float2*)&stg[(m0l + 8 + g) * STG_STRIDE + col] =
                    make_float2(acc[nt * 4 + 2], acc[nt * 4 + 3]);
            }
        }
        __syncthreads();

        const int er = tid >> 4;             // 0..31
        const int eL = wave * 32 + er;
        const int c0 = (tid & 15) * 8;
        const int j = js[eL], i = is_[eL];
        const float ev0 = evs[eL * 3 + 0], ev1 = evs[eL * 3 + 1], ev2 = evs[eL * 3 + 2];
        const float* xh = g_xh + (size_t)j * 384;
        const float* vp = vec + (size_t)j * 384;
        float* dxp = d_x + (size_t)i * 128;
        float* dvp = d_vec + (size_t)i * 384;
        const float* srow = stg + er * STG_STRIDE;

#pragma unroll
        for (int g2 = 0; g2 < 2; g2++) {
            const int c = c0 + g2 * 4;
            float4 r1 = *(const float4*)(srow + c);
            float4 r2 = *(const float4*)(srow + 128 + c);
            float4 r3 = *(const float4*)(srow + 256 + c);
            float4 b0 = *(const float4*)(bes + c);
            float4 b1v = *(const float4*)(bes + 128 + c);
            float4 b2v = *(const float4*)(bes + 256 + c);
            float4 x1 = *(const float4*)(xh + c);
            float4 x2 = *(const float4*)(xh + 128 + c);
            float4 x3 = *(const float4*)(xh + 256 + c);

            float m1[4], m2[4];
            m1[0] = (r1.x + b0.x) * x1.x * s3;
            m1[1] = (r1.y + b0.y) * x1.y * s3;
            m1[2] = (r1.z + b0.z) * x1.z * s3;
            m1[3] = (r1.w + b0.w) * x1.w * s3;
            m2[0] = (r2.x + b1v.x) * x2.x * s3;
            m2[1] = (r2.y + b1v.y) * x2.y * s3;
            m2[2] = (r2.z + b1v.z) * x2.z * s3;
            m2[3] = (r2.w + b1v.w) * x2.w * s3;
            float4 ox;
            ox.x = (r3.x + b2v.x) * x3.x * s3;
            ox.y = (r3.y + b2v.y) * x3.y * s3;
            ox.z = (r3.z + b2v.z) * x3.z * s3;
            ox.w = (r3.w + b2v.w) * x3.w * s3;
            RED4(dxp + c, ox);

#pragma unroll
            for (int d = 0; d < 3; d++) {
                const float evd = (d == 0) ? ev0 : (d == 1) ? ev1 : ev2;
                float4 vj = *(const float4*)(vp + d * 128 + c);
                float4 o;
                o.x = (m1[0] * vj.x + m2[0] * evd) * sH;
                o.y = (m1[1] * vj.y + m2[1] * evd) * sH;
                o.z = (m1[2] * vj.z + m2[2] * evd) * sH;
                o.w = (m1[3] * vj.w + m2[3] * evd) * sH;
                RED4(dvp + d * 128 + c, o);
            }
        }
        __syncthreads();
    }
}

// ---------------- launch ----------------
extern "C" void kernel_launch(void* const* d_in, const int* in_sizes, int n_in,
                              void* d_out, int out_size)
{
    const float *x = nullptr, *vec = nullptr, *erbf = nullptr, *evec = nullptr;
    const float *W1 = nullptr, *b1 = nullptr, *W2 = nullptr, *b2 = nullptr;
    const float *We = nullptr, *be = nullptr;
    const int* eidx = nullptr;

    int seen384 = 0;
    for (int idx = 0; idx < n_in; idx++) {
        int s = in_sizes[idx];
        const void* p = d_in[idx];
        switch (s) {
            case 6400000:   x    = (const float*)p; break;
            case 19200000:  vec  = (const float*)p; break;
            case 102400000: erbf = (const float*)p; break;
            case 2400000:   evec = (const float*)p; break;
            case 1600000:   eidx = (const int*)p; break;
            case 8192:      W1   = (const float*)p; break;
            case 64:        b1   = (const float*)p; break;
            case 24576:     W2   = (const float*)p; break;
            case 49152:     We   = (const float*)p; break;
            case 384:
                if (seen384 == 0) b2 = (const float*)p; else be = (const float*)p;
                seen384++;
                break;
            default: break;
        }
    }

    float* out   = (float*)d_out;
    float* d_x   = out;
    float* d_vec = out + (size_t)NN * HH;

    cudaFuncSetAttribute(edge_kernel, cudaFuncAttributeMaxDynamicSharedMemorySize, EDGE_SMEM);

    long long n4 = out_size / 4;
    zero_kernel<<<(unsigned)((n4 + 255) / 256), 256>>>((float4*)out, n4);
    prep_we<<<192, 256>>>(We);
    node_kernel<<<NN / 16, 384>>>(x, W1, b1, W2, b2);
    edge_kernel<<<EE / 64, 512, EDGE_SMEM>>>(erbf, evec, eidx, be, vec, d_x, d_vec);
}

// round 6
// speedup vs baseline: 1.4403x; 1.0434x over previous
#include <cuda_runtime.h>
#include <cuda_bf16.h>
#include <cstdint>

#define NN 50000
#define EE 800000
#define HH 128
#define TH 384

// scratch: x_h [N][384] fp32; We pre-split bf16 hi/lo packed per (colgroup, kchunk, half)
__device__ __align__(16) float g_xh[(size_t)NN * TH];
// layout: ((g*8 + kc)*2 + half)*3072 + rr*32 + ((k>>3)&1)*16 + (k&7)*2
//   rr = s*48 + chunk*16 + u   (n = chunk*128 + g*32 + s*16 + u)
__device__ __align__(16) unsigned char g_WeB[4 * 8 * 2 * 3072];   // 196608 B

// ---------------- PTX helpers ----------------
#define PACK2(d, lo, hi) \
    asm volatile("mov.b64 %0, {%1, %2};" : "=l"(d) : "f"(lo), "f"(hi))
#define UNPACK2(lo, hi, s) \
    asm volatile("mov.b64 {%0, %1}, %2;" : "=f"(lo), "=f"(hi) : "l"(s))
#define FMA2(c_, a_, b_) \
    asm volatile("fma.rn.f32x2 %0, %1, %2, %0;" : "+l"(c_) : "l"(a_), "l"(b_))
#define RED4(p_, v_) \
    asm volatile("red.global.add.v4.f32 [%0], {%1, %2, %3, %4};" \
                 :: "l"(p_), "f"((v_).x), "f"((v_).y), "f"((v_).z), "f"((v_).w) : "memory")
#define CP_ASYNC16(dst_s, src_g) \
    asm volatile("cp.async.cg.shared.global [%0], [%1], 16;" :: "r"(dst_s), "l"(src_g))
#define CP_COMMIT() asm volatile("cp.async.commit_group;")
#define CP_WAIT0()  asm volatile("cp.async.wait_group 0;")
#define CP_WAIT1()  asm volatile("cp.async.wait_group 1;")

#define LDSM4(f_, addr_) \
    asm volatile("ldmatrix.sync.aligned.m8n8.x4.shared.b16 {%0,%1,%2,%3}, [%4];" \
        : "=r"((f_)[0]), "=r"((f_)[1]), "=r"((f_)[2]), "=r"((f_)[3]) : "r"(addr_))
#define MMA(c_, a_, b0_, b1_) \
    asm volatile("mma.sync.aligned.m16n8k16.row.col.f32.bf16.bf16.f32 " \
        "{%0,%1,%2,%3}, {%4,%5,%6,%7}, {%8,%9}, {%0,%1,%2,%3};" \
        : "+f"((c_)[0]), "+f"((c_)[1]), "+f"((c_)[2]), "+f"((c_)[3]) \
        : "r"((a_)[0]), "r"((a_)[1]), "r"((a_)[2]), "r"((a_)[3]), "r"(b0_), "r"(b1_))

// ---------------- zero output ----------------
__global__ void zero_kernel(float4* __restrict__ p, long long n4) {
    long long i = (long long)blockIdx.x * blockDim.x + threadIdx.x;
    if (i < n4) p[i] = make_float4(0.f, 0.f, 0.f, 0.f);
}

// ---------------- prep: We [K=128][N=384] fp32 -> bf16 hi/lo packed ----------------
__global__ void prep_we(const float* __restrict__ We) {
    int idx = blockIdx.x * 256 + threadIdx.x;    // n*128 + k
    if (idx >= 384 * 128) return;
    int n = idx >> 7, k = idx & 127;
    float v = We[(size_t)k * 384 + n];
    __nv_bfloat16 h = __float2bfloat16(v);
    __nv_bfloat16 l = __float2bfloat16(v - __bfloat162float(h));
    int chunk = n >> 7, rem = n & 127;
    int g = rem >> 5, w32 = rem & 31;
    int s = w32 >> 4, u = w32 & 15;
    int rr = s * 48 + chunk * 16 + u;
    int kc = k >> 4, kin = k & 15;
    uint32_t off = (uint32_t)(((g * 8 + kc) * 2) * 3072 + rr * 32
                              + ((kin >> 3) & 1) * 16 + (kin & 7) * 2);
    *(unsigned short*)(g_WeB + off)        = __bfloat16_as_ushort(h);
    *(unsigned short*)(g_WeB + off + 3072) = __bfloat16_as_ushort(l);
}

// ---------------- node kernel (unchanged FFMA2 path) ----------------
__global__ __launch_bounds__(384) void node_kernel(
    const float* __restrict__ x, const float* __restrict__ W1,
    const float* __restrict__ b1, const float* __restrict__ W2,
    const float* __restrict__ b2)
{
    __shared__ __align__(16) float xs[128 * 16];
    __shared__ __align__(16) float w1s[128 * 64];
    __shared__ __align__(16) float hs[64 * 20];

    const int t = threadIdx.x;
    const int node0 = blockIdx.x * 16;

    for (int i = t; i < 8192; i += 384) w1s[i] = W1[i];
    const float4* x4 = (const float4*)x;
    for (int idx = t; idx < 512; idx += 384) {
        int n = idx & 15, kq = idx >> 4;
        float4 v = x4[(size_t)(node0 + n) * 32 + kq];
        xs[(kq * 4 + 0) * 16 + n] = v.x;
        xs[(kq * 4 + 1) * 16 + n] = v.y;
        xs[(kq * 4 + 2) * 16 + n] = v.z;
        xs[(kq * 4 + 3) * 16 + n] = v.w;
    }
    __syncthreads();

    for (int idx = t; idx < 1024; idx += 384) {
        int n = idx & 15, c = idx >> 4;
        float acc = b1[c];
#pragma unroll 8
        for (int k = 0; k < 128; k++) acc += xs[k * 16 + n] * w1s[k * 64 + c];
        float hv = acc / (1.f + __expf(-acc)) * 1.6666666666666667f;
        hs[c * 20 + n] = hv;
    }
    __syncthreads();

    const int c = t;
    unsigned long long acc2[8];
#pragma unroll
    for (int p = 0; p < 8; p++) acc2[p] = 0ull;
#pragma unroll 4
    for (int k = 0; k < 64; k++) {
        float w = W2[k * 384 + c];
        unsigned long long wp; PACK2(wp, w, w);
        const unsigned long long* hp = (const unsigned long long*)&hs[k * 20];
#pragma unroll
        for (int p = 0; p < 8; p++) { unsigned long long hv = hp[p]; FMA2(acc2[p], hv, wp); }
    }
    const float bc = b2[c];
#pragma unroll
    for (int p = 0; p < 8; p++) {
        float lo, hi; UNPACK2(lo, hi, acc2[p]);
        g_xh[(size_t)(node0 + 2 * p) * 384 + c] = lo + bc;
        g_xh[(size_t)(node0 + 2 * p + 1) * 384 + c] = hi + bc;
    }
}

// ---------------- edge kernel ----------------
// 256 threads, M=64 edges x N=96 GEMM cols (col-group g: cols {g*32..}+0/128/256).
// grid = 12500 edge-tiles * 4 col groups, col group fastest (L2 reuse of rbf tile).
// 8 warps: mband = wid&3 (16 rows), nslice = wid>>2 (48 cols).
// smem:
//   [0:256) js  [256:512) is  [512:1280) evs[192]  [1280:2816) bes[384]
//   [4096:20480)  A hi 64x128 bf16 swizzled   [20480:36864) A lo
//   [36864:64512) B triple buffer: buf b at +b*9216 { hi 96x48B, lo +4608 }
//   stage (post-MMA, reuses B): fp32 [64][100] at 36864
#define A_OFF 4096
#define B_OFF 36864
#define EDGE_SMEM 64512
#define STG 100

__global__ __launch_bounds__(256, 3) void edge_kernel(
    const float* __restrict__ edge_rbf, const float* __restrict__ edge_vector,
    const int* __restrict__ edge_index, const float* __restrict__ be,
    const float* __restrict__ vec, float* __restrict__ d_x, float* __restrict__ d_vec)
{
    extern __shared__ __align__(16) unsigned char sm[];
    const uint32_t smb = (uint32_t)__cvta_generic_to_shared(sm);
    const int tid = threadIdx.x;
    const int wid = tid >> 5;
    const int lane = tid & 31;
    const int g = blockIdx.x & 3;
    const int e0 = (blockIdx.x >> 2) * 64;

    int* js   = (int*)(sm);
    int* is_  = (int*)(sm + 256);
    float* evs = (float*)(sm + 512);
    float* bes = (float*)(sm + 1280);

    if (tid < 64) {
        js[tid]  = edge_index[e0 + tid];
        is_[tid] = edge_index[EE + e0 + tid];
    }
    if (tid < 192) evs[tid] = edge_vector[(size_t)e0 * 3 + tid];
    for (int id = tid; id < 384; id += 256) bes[id] = be[id];

    // ---- A: load fp32 rbf, split bf16 hi/lo, swizzled store ----
    const float4* rbf4 = (const float4*)edge_rbf;
#pragma unroll
    for (int r = 0; r < 8; r++) {
        int fid = tid + r * 256;            // 0..2047
        int e = fid >> 5, q = fid & 31;     // edge row, float4 index (k0 = q*4)
        float4 v = rbf4[(size_t)(e0 + e) * 32 + q];
        float vv[4] = {v.x, v.y, v.z, v.w};
        unsigned short hb[4], lb[4];
#pragma unroll
        for (int u = 0; u < 4; u++) {
            __nv_bfloat16 h = __float2bfloat16(vv[u]);
            __nv_bfloat16 l = __float2bfloat16(vv[u] - __bfloat162float(h));
            hb[u] = __bfloat16_as_ushort(h);
            lb[u] = __bfloat16_as_ushort(l);
        }
        uint2 ph = make_uint2((uint32_t)hb[0] | ((uint32_t)hb[1] << 16),
                              (uint32_t)hb[2] | ((uint32_t)hb[3] << 16));
        uint2 pl = make_uint2((uint32_t)lb[0] | ((uint32_t)lb[1] << 16),
                              (uint32_t)lb[2] | ((uint32_t)lb[3] << 16));
        uint32_t addr = (uint32_t)(e * 256 + (((q >> 1) ^ (e & 7)) << 4) + (q & 1) * 8);
        *(uint2*)(sm + A_OFF + addr)         = ph;
        *(uint2*)(sm + A_OFF + 16384 + addr) = pl;
    }

    // ---- prefetch B chunk 0 into buf 0 ----
    const unsigned char* bsrc0 = g_WeB + (size_t)(g * 8) * 6144;
    for (int id = tid; id < 384; id += 256) {
        int half = id / 192, rem = id - half * 192;
        int rr = rem >> 1, u16 = rem & 1;
        CP_ASYNC16(smb + B_OFF + half * 4608 + rr * 48 + u16 * 16,
                   bsrc0 + half * 3072 + rr * 32 + u16 * 16);
    }
    CP_COMMIT();

    // ---- per-warp frag addressing ----
    const int m0 = (wid & 3) * 16;
    const int s = wid >> 2;                      // nslice (48 cols)
    const int am = m0 + (lane & 15);
    const uint32_t a_row = smb + A_OFF + am * 256;
    const int a_kpar = lane >> 4;
    const int a_sw = lane & 7;
    const uint32_t b_row = (uint32_t)((s * 48 + ((lane >> 4) << 3) + (lane & 7)) * 48
                                      + (((lane >> 3) & 1) << 4));

    float acc[24];
#pragma unroll
    for (int i = 0; i < 24; i++) acc[i] = 0.f;

    for (int kc = 0; kc < 8; kc++) {
        if (kc < 7) {
            const unsigned char* src = g_WeB + (size_t)(g * 8 + kc + 1) * 6144;
            uint32_t dst = smb + B_OFF + ((kc + 1) % 3) * 9216;
            for (int id = tid; id < 384; id += 256) {
                int half = id / 192, rem = id - half * 192;
                int rr = rem >> 1, u16 = rem & 1;
                CP_ASYNC16(dst + half * 4608 + rr * 48 + u16 * 16,
                           src + half * 3072 + rr * 32 + u16 * 16);
            }
            CP_COMMIT();
            CP_WAIT1();
        } else {
            CP_WAIT0();
        }
        __syncthreads();

        uint32_t ah[4], al[4];
        {
            uint32_t aaddr = a_row + (((kc * 2 + a_kpar) ^ a_sw) << 4);
            LDSM4(ah, aaddr);
            LDSM4(al, aaddr + 16384);
        }
        const uint32_t bb = smb + B_OFF + (kc % 3) * 9216 + b_row;
#pragma unroll
        for (int p = 0; p < 3; p++) {
            uint32_t bh[4], bl[4];
            uint32_t baddr = bb + p * 768;        // 16 rows * 48B
            LDSM4(bh, baddr);
            LDSM4(bl, baddr + 4608);
            float* cA = acc + p * 8;
            float* cB = acc + p * 8 + 4;
            MMA(cA, ah, bh[0], bh[1]);
            MMA(cA, al, bh[0], bh[1]);
            MMA(cA, ah, bl[0], bl[1]);
            MMA(cB, ah, bh[2], bh[3]);
            MMA(cB, al, bh[2], bh[3]);
            MMA(cB, ah, bl[2], bl[3]);
        }
    }

    // ---------------- stage fragments ----------------
    __syncthreads();
    float* stg = (float*)(sm + B_OFF);
    {
        const int r0 = m0 + (lane >> 2);
        const int cb = s * 16 + (lane & 3) * 2;
#pragma unroll
        for (int ch = 0; ch < 3; ch++)
#pragma unroll
            for (int sub = 0; sub < 2; sub++) {
                int col = ch * 32 + cb + sub * 8;
                *(float2*)&stg[r0 * STG + col] =
                    make_float2(acc[ch * 8 + sub * 4 + 0], acc[ch * 8 + sub * 4 + 1]);
                *(float2*)&stg[(r0 + 8) * STG + col] =
                    make_float2(acc[ch * 8 + sub * 4 + 2], acc[ch * 8 + sub * 4 + 3]);
            }
    }
    __syncthreads();

    // ---------------- fused epilogue: gather + scatter ----------------
    const float s3 = 0.5773502691896258f;    // 1/sqrt(3)
    const float sH = 0.08838834764831845f;   // 1/sqrt(128)
    const int e = tid >> 2;                  // 0..63
    const int q = tid & 3;                   // 8-col slot
    const int cl = g * 32 + q * 8;           // within-chunk col base (0..127)
    const int j = js[e], i = is_[e];
    const float ev0 = evs[e * 3 + 0], ev1 = evs[e * 3 + 1], ev2 = evs[e * 3 + 2];
    const float* xh = g_xh + (size_t)j * 384;
    const float* vp = vec + (size_t)j * 384;
    float* dxp = d_x + (size_t)i * 128;
    float* dvp = d_vec + (size_t)i * 384;
    const float* srow = stg + e * STG + q * 8;

#pragma unroll
    for (int g2 = 0; g2 < 2; g2++) {
        const int c = cl + g2 * 4;                     // chunk-local col
        float4 r1 = *(const float4*)(srow + g2 * 4);
        float4 r2 = *(const float4*)(srow + 32 + g2 * 4);
        float4 r3 = *(const float4*)(srow + 64 + g2 * 4);
        float4 b0 = *(const float4*)(bes + c);
        float4 b1v = *(const float4*)(bes + 128 + c);
        float4 b2v = *(const float4*)(bes + 256 + c);
        float4 x1 = *(const float4*)(xh + c);
        float4 x2 = *(const float4*)(xh + 128 + c);
        float4 x3 = *(const float4*)(xh + 256 + c);

        float m1[4], m2[4];
        m1[0] = (r1.x + b0.x) * x1.x * s3;
        m1[1] = (r1.y + b0.y) * x1.y * s3;
        m1[2] = (r1.z + b0.z) * x1.z * s3;
        m1[3] = (r1.w + b0.w) * x1.w * s3;
        m2[0] = (r2.x + b1v.x) * x2.x * s3;
        m2[1] = (r2.y + b1v.y) * x2.y * s3;
        m2[2] = (r2.z + b1v.z) * x2.z * s3;
        m2[3] = (r2.w + b1v.w) * x2.w * s3;
        float4 ox;
        ox.x = (r3.x + b2v.x) * x3.x * s3;
        ox.y = (r3.y + b2v.y) * x3.y * s3;
        ox.z = (r3.z + b2v.z) * x3.z * s3;
        ox.w = (r3.w + b2v.w) * x3.w * s3;
        RED4(dxp + c, ox);

#pragma unroll
        for (int d = 0; d < 3; d++) {
            const float evd = (d == 0) ? ev0 : (d == 1) ? ev1 : ev2;
            float4 vj = *(const float4*)(vp + d * 128 + c);
            float4 o;
            o.x = (m1[0] * vj.x + m2[0] * evd) * sH;
            o.y = (m1[1] * vj.y + m2[1] * evd) * sH;
            o.z = (m1[2] * vj.z + m2[2] * evd) * sH;
            o.w = (m1[3] * vj.w + m2[3] * evd) * sH;
            RED4(dvp + d * 128 + c, o);
        }
    }
}

// ---------------- launch ----------------
extern "C" void kernel_launch(void* const* d_in, const int* in_sizes, int n_in,
                              void* d_out, int out_size)
{
    const float *x = nullptr, *vec = nullptr, *erbf = nullptr, *evec = nullptr;
    const float *W1 = nullptr, *b1 = nullptr, *W2 = nullptr, *b2 = nullptr;
    const float *We = nullptr, *be = nullptr;
    const int* eidx = nullptr;

    int seen384 = 0;
    for (int idx = 0; idx < n_in; idx++) {
        int s = in_sizes[idx];
        const void* p = d_in[idx];
        switch (s) {
            case 6400000:   x    = (const float*)p; break;
            case 19200000:  vec  = (const float*)p; break;
            case 102400000: erbf = (const float*)p; break;
            case 2400000:   evec = (const float*)p; break;
            case 1600000:   eidx = (const int*)p; break;
            case 8192:      W1   = (const float*)p; break;
            case 64:        b1   = (const float*)p; break;
            case 24576:     W2   = (const float*)p; break;
            case 49152:     We   = (const float*)p; break;
            case 384:
                if (seen384 == 0) b2 = (const float*)p; else be = (const float*)p;
                seen384++;
                break;
            default: break;
        }
    }

    float* out   = (float*)d_out;
    float* d_x   = out;
    float* d_vec = out + (size_t)NN * HH;

    cudaFuncSetAttribute(edge_kernel, cudaFuncAttributeMaxDynamicSharedMemorySize, EDGE_SMEM);

    long long n4 = out_size / 4;
    zero_kernel<<<(unsigned)((n4 + 255) / 256), 256>>>((float4*)out, n4);
    prep_we<<<192, 256>>>(We);
    node_kernel<<<NN / 16, 384>>>(x, W1, b1, W2, b2);
    edge_kernel<<<(EE / 64) * 4, 256, EDGE_SMEM>>>(erbf, evec, eidx, be, vec, d_x, d_vec);
}